// round 17
// baseline (speedup 1.0000x reference)
#include <cuda_runtime.h>
#include <math.h>

#define BB   64
#define LL   65536
#define NW   2047
#define WPB  128
#define BPB  16
#define HID  512
#define DM   256
#define SD   321

#define NMLP  128
#define NWINW 160
#define NBLK  (NMLP + NWINW)   // 288 <= 296 (2/SM residency) -> 1 wave
#define NJOB  (BB * BPB)       // 1024 win tiles

// ---------------- scratch (__device__ globals; no allocation allowed) -------
__device__ unsigned int g_hist_parts[BB * BPB * 256];
__device__ float g_went[BB * NW];
__device__ float g_feats[BB * SD];
__device__ float g_z1p[4][BB * HID];
__device__ float g_z2p[4][BB * HID];
__device__ float g_outp[8][BB * DM];
__device__ unsigned int g_wcnt[BB];      // per-row win completion (target 16)
__device__ unsigned int g_cnt[4][8];     // [stage][rowgroup]
__device__ unsigned int g_fin;           // fin acks (target 64)

// ---------------- dataflow sync helpers --------------------------------------
__device__ __forceinline__ void publish(unsigned int* c) {
    __syncthreads();
    __threadfence();
    if (threadIdx.x == 0) atomicAdd(c, 1u);
}
__device__ __forceinline__ void waitc(unsigned int* c, unsigned int tgt) {
    __syncthreads();
    if (threadIdx.x == 0) {
        volatile unsigned int* p = c;
        while (*p < tgt) {}
        __threadfence();
    }
    __syncthreads();
}

// GEMM stage: 128 jobs, tile 8r x 128c, split-K, W streamed via 16-row
// double-buffered smem chunks. Thread tile 2x2.
// MODE 1: A=g_feats (K=321) CH=96  ct4 ks4 -> g_z1p[4]
// MODE 2: A=relu(LN(sum z1p + b1)) CH=128 ct4 ks4 -> g_z2p[4]
// MODE 3: A=relu(LN(sum z2p + b2)) CH=64  ct2 ks8 -> g_outp[8]  (N=256)
template <int MODE>
__device__ void mlp_gemm(float (*s_w)[16][128], float (*s_a)[10],
                         const float* __restrict__ W,
                         const float* __restrict__ bias,
                         const float* __restrict__ gam,
                         const float* __restrict__ bet) {
    constexpr int CH  = (MODE == 1) ? 96 : ((MODE == 2) ? 128 : 64);
    constexpr int NCH = CH / 16;
    constexpr int N   = (MODE == 3) ? DM : HID;
    constexpr int K   = (MODE == 1) ? SD : HID;

    const int job = blockIdx.x;
    int ct, rg, ks;
    if (MODE == 3) { ct = job & 1; rg = (job >> 1) & 7; ks = job >> 4; }
    else           { ct = job & 3; rg = (job >> 2) & 7; ks = job >> 5; }
    const int c0 = ct * 128, r0 = rg * 8, k0 = ks * CH;

    if (MODE == 1) waitc(&g_cnt[0][rg], 8);
    else           waitc(&g_cnt[MODE - 1][rg], 16);

    const int tid  = threadIdx.x;
    const int lane = tid & 31;
    const int w    = tid >> 5;

    // ---- stage A ----
    if (MODE == 1) {
        for (int idx = tid; idx < 8 * CH; idx += 256) {
            const int r = idx / CH, k = idx - r * CH;
            float v = 0.f;
            if ((k0 + k) < K) v = g_feats[(r0 + r) * SD + k0 + k];
            s_a[k][r] = v;
        }
    } else {
        const float* P = (MODE == 2) ? &g_z1p[0][0] : &g_z2p[0][0];
        const int r = r0 + w;
        float zv[16];
        float sum = 0.f;
        #pragma unroll
        for (int i = 0; i < 16; i++) {
            const int k = lane + 32 * i;
            float z = bias[k];
            #pragma unroll
            for (int s = 0; s < 4; s++) z += P[(long)s * (BB * HID) + r * HID + k];
            zv[i] = z; sum += z;
        }
        #pragma unroll
        for (int o = 16; o; o >>= 1) sum += __shfl_xor_sync(0xffffffffu, sum, o);
        const float mu = sum * (1.0f / 512.0f);
        float vs = 0.f;
        #pragma unroll
        for (int i = 0; i < 16; i++) { const float d = zv[i] - mu; vs += d * d; }
        #pragma unroll
        for (int o = 16; o; o >>= 1) vs += __shfl_xor_sync(0xffffffffu, vs, o);
        const float rstd = rsqrtf(vs * (1.0f / 512.0f) + 1e-5f);
        #pragma unroll
        for (int j = 0; j < CH / 32; j++) {
            const int i = (k0 >> 5) + j;
            const int k = lane + 32 * i;
            const float hv = (zv[i] - mu) * rstd * gam[k] + bet[k];
            s_a[k - k0][w] = fmaxf(hv, 0.0f);
        }
    }

    // ---- W chunks: 16 rows x 128 cols, double-buffered from global ----
    const int r0w = tid >> 5,          c40 = (tid & 31) * 4;
    const int r1w = (tid + 256) >> 5,  c41 = c40;

    float4 p0, p1;
    {
        int ka = k0 + r0w, kb = k0 + r1w;
        if (MODE == 1) { if (ka >= K) ka = K - 1; if (kb >= K) kb = K - 1; }
        p0 = *(const float4*)&W[(long)ka * N + c0 + c40];
        p1 = *(const float4*)&W[(long)kb * N + c0 + c41];
    }
    *(float4*)&s_w[0][r0w][c40] = p0;
    *(float4*)&s_w[0][r1w][c41] = p1;

    const int rp = tid >> 6, cp = tid & 63;
    float a00 = 0.f, a01 = 0.f, a10 = 0.f, a11 = 0.f;
    #pragma unroll
    for (int c = 0; c < NCH; c++) {
        if (c + 1 < NCH) {
            int ka = k0 + (c + 1) * 16 + r0w;
            int kb = k0 + (c + 1) * 16 + r1w;
            if (MODE == 1) { if (ka >= K) ka = K - 1; if (kb >= K) kb = K - 1; }
            p0 = *(const float4*)&W[(long)ka * N + c0 + c40];
            p1 = *(const float4*)&W[(long)kb * N + c0 + c41];
        }
        __syncthreads();
        const int bs = c & 1;
        #pragma unroll
        for (int kk = 0; kk < 16; kk++) {
            const float2 wv = *(const float2*)&s_w[bs][kk][cp * 2];
            const float2 av = *(const float2*)&s_a[c * 16 + kk][rp * 2];
            a00 = fmaf(av.x, wv.x, a00);
            a01 = fmaf(av.x, wv.y, a01);
            a10 = fmaf(av.y, wv.x, a10);
            a11 = fmaf(av.y, wv.y, a11);
        }
        if (c + 1 < NCH) {
            *(float4*)&s_w[bs ^ 1][r0w][c40] = p0;
            *(float4*)&s_w[bs ^ 1][r1w][c41] = p1;
        }
    }

    float* OP = (MODE == 1) ? &g_z1p[0][0] : ((MODE == 2) ? &g_z2p[0][0] : &g_outp[0][0]);
    const long base = (long)ks * (BB * N);
    const int r = r0 + rp * 2, cc = c0 + cp * 2;
    *(float2*)&OP[base + (long)r * N + cc]       = make_float2(a00, a01);
    *(float2*)&OP[base + (long)(r + 1) * N + cc] = make_float2(a10, a11);

    publish(&g_cnt[MODE][rg]);
}

// ---------------- single mega-kernel: win workers + MLP pipeline -------------
__global__ void __launch_bounds__(256, 2) mega_kernel(
    const int* __restrict__ x,
    const float* __restrict__ W1, const float* __restrict__ b1,
    const float* __restrict__ g1, const float* __restrict__ be1,
    const float* __restrict__ W2, const float* __restrict__ b2,
    const float* __restrict__ g2, const float* __restrict__ be2,
    const float* __restrict__ W3, const float* __restrict__ b3,
    float* __restrict__ out) {
    // ALL vector-accessed shared arrays explicitly 16B-aligned (R16 crash fix)
    __shared__ __align__(16) unsigned char s_x[4128 + 32];
    __shared__ __align__(16) unsigned int s_hist[8][64];
    __shared__ __align__(16) unsigned int s_part[256];
    __shared__ __align__(16) float        s_lut[68];
    __shared__ __align__(16) float s_w[2][16][128];
    __shared__ __align__(16) float s_a[128][10];
    __shared__ __align__(16) unsigned int s_cnt[64];
    __shared__ __align__(16) float s_lev[64];
    __shared__ __align__(16) float s_wred[8];

    const int tid  = threadIdx.x;
    const int lane = tid & 31;
    const int warp = tid >> 5;

    if (blockIdx.x >= NMLP) {
        // ================= WIN WORKER =================
        const int wkr = blockIdx.x - NMLP;     // 0..159
        if (tid <= 64) {
            if (tid == 0) s_lut[0] = 0.0f;
            else {
                float p = (float)tid * (1.0f / 64.0f);
                float t = -(p * log2f(p + 1e-10f));
                s_lut[tid] = t / (float)tid;
            }
        }
        for (int j = wkr; j < NJOB; j += NWINW) {
            const int b   = j >> 4;
            const int blk = j & 15;
            const int wstart = blk * WPB;
            const int wcount = min(WPB, NW - wstart);
            const int span   = (wcount - 1) * 32 + 64;
            const long base  = (long)b * LL + (long)blk * (WPB * 32);

            s_part[tid] = 0u;
            {
                const int4* xv = (const int4*)(x + base);
                uchar4* sv = (uchar4*)s_x;
                const int n4 = span >> 2;
                for (int i = tid; i < n4; i += 256) {
                    int4 v = xv[i];
                    sv[i] = make_uchar4((unsigned char)min(max(v.x, 0), 255),
                                        (unsigned char)min(max(v.y, 0), 255),
                                        (unsigned char)min(max(v.z, 0), 255),
                                        (unsigned char)min(max(v.w, 0), 255));
                }
            }
            __syncthreads();

            for (int i = tid; i < 4096; i += 256)
                atomicAdd(&s_part[s_x[i]], 1u);

            unsigned int* hist = s_hist[warp];
            for (int wi = warp; wi < wcount; wi += 8) {
                const int off = wi * 32;
                hist[lane]      = 0u;
                hist[lane + 32] = 0u;
                __syncwarp();
                const int va = s_x[off + lane];
                const int vb = s_x[off + 32 + lane];
                atomicAdd(&hist[va >> 2], 1u << ((va & 3) << 3));
                atomicAdd(&hist[vb >> 2], 1u << ((vb & 3) << 3));
                __syncwarp();
                const unsigned ca = (hist[va >> 2] >> ((va & 3) << 3)) & 0xFFu;
                const unsigned cb = (hist[vb >> 2] >> ((vb & 3) << 3)) & 0xFFu;
                float h = s_lut[ca] + s_lut[cb];
                #pragma unroll
                for (int o = 16; o; o >>= 1) h += __shfl_xor_sync(0xffffffffu, h, o);
                if (lane == 0) g_went[b * NW + wstart + wi] = h;
            }
            __syncthreads();
            g_hist_parts[(b * BPB + blk) * 256 + tid] = s_part[tid];
            publish(&g_wcnt[b]);          // row-level completion signal
        }
        return;
    }

    // ================= MLP PIPELINE (blocks 0-127) =================
    const int job = blockIdx.x;

    // ---- feat: blocks 0-63, gated on win row counters ----
    if (job < BB) {
        const int b = job;
        waitc(&g_wcnt[b], 16);
        if (tid == 0) g_wcnt[b] = 0u;     // sole reader: safe reset for replay

        float term = 0.0f;
        {
            unsigned int c = 0;
            #pragma unroll
            for (int p = 0; p < BPB; p++)
                c += g_hist_parts[(b * BPB + p) * 256 + tid];
            const float nh = (float)c * (1.0f / 65536.0f);
            g_feats[b * SD + tid] = nh;
            term = -(nh * log2f(nh + 1e-10f));
        }
        if (tid < 64) {
            s_lev[tid] = (tid == 63) ? 8.0f : (float)tid * (8.0f / 63.0f);
            s_cnt[tid] = 0u;
        }
        {
            float t = term;
            #pragma unroll
            for (int o = 16; o; o >>= 1) t += __shfl_xor_sync(0xffffffffu, t, o);
            if (lane == 0) s_wred[warp] = t;
            __syncthreads();
            if (tid == 0) {
                float u = 0.f;
                #pragma unroll
                for (int i = 0; i < 8; i++) u += s_wred[i];
                g_feats[b * SD + 256] = u;
            }
        }

        for (int i = tid; i < NW; i += 256) {
            const float h = g_went[b * NW + i];
            int j = (int)(h * 7.875f);
            j = min(max(j, 0), 63);
            while (j > 0 && h <= s_lev[j - 1]) j--;
            while (j < 63 && h > s_lev[j]) j++;
            const unsigned m = __match_any_sync(__activemask(), j);
            if ((m & ((1u << lane) - 1u)) == 0u)
                atomicAdd(&s_cnt[j], (unsigned)__popc(m));
        }
        __syncthreads();
        #pragma unroll
        for (int o = 1; o < 64; o <<= 1) {
            unsigned v = 0;
            if (tid < 64 && tid >= o) v = s_cnt[tid - o];
            __syncthreads();
            if (tid < 64) s_cnt[tid] += v;
            __syncthreads();
        }
        if (tid < 64)
            g_feats[b * SD + 257 + tid] = (float)s_cnt[tid] / 2047.0f;
        publish(&g_cnt[0][b >> 3]);
    }

    mlp_gemm<1>(s_w, s_a, W1, nullptr, nullptr, nullptr);
    mlp_gemm<2>(s_w, s_a, W2, b1, g1, be1);
    mlp_gemm<3>(s_w, s_a, W3, b2, g2, be2);

    // ---- finalize: blocks 0-63, one row each ----
    if (job < BB) {
        waitc(&g_cnt[3][job >> 3], 16);
        const int i = job * DM + tid;
        float v = b3[tid];
        #pragma unroll
        for (int s = 0; s < 8; s++) v += g_outp[s][i];
        out[i] = v;
        __syncthreads();
        if (tid == 0) { __threadfence(); atomicAdd(&g_fin, 1u); }
    }

    // ---- cleanup: block 0 resets stage counters after all fin acks ----
    // (safe: g_fin==64 implies every waitc in the kernel has already passed)
    if (job == 0) {
        if (tid == 0) {
            volatile unsigned int* p = &g_fin;
            while (*p < BB) {}
        }
        __syncthreads();
        if (tid < 32) ((unsigned int*)g_cnt)[tid] = 0u;
        if (tid == 32) g_fin = 0u;
        __threadfence();
    }
}

// ---------------- launch: ONE kernel, graph-capture-safe ---------------------
extern "C" void kernel_launch(void* const* d_in, const int* in_sizes, int n_in,
                              void* d_out, int out_size) {
    const int*   x   = (const int*)d_in[0];
    const float* W1  = (const float*)d_in[1];
    const float* b1  = (const float*)d_in[2];
    const float* g1  = (const float*)d_in[3];
    const float* be1 = (const float*)d_in[4];
    const float* W2  = (const float*)d_in[5];
    const float* b2  = (const float*)d_in[6];
    const float* g2  = (const float*)d_in[7];
    const float* be2 = (const float*)d_in[8];
    const float* W3  = (const float*)d_in[9];
    const float* b3  = (const float*)d_in[10];
    float* out = (float*)d_out;

    mega_kernel<<<NBLK, 256>>>(x, W1, b1, g1, be1, W2, b2, g2, be2, W3, b3, out);
}